// round 11
// baseline (speedup 1.0000x reference)
#include <cuda_runtime.h>
#include <cstdint>

// ---------------------------------------------------------------------------
// Problem constants
// ---------------------------------------------------------------------------
constexpr int B   = 2;
constexpr int S   = 2048;
constexpr int H   = 2048;
constexpr int NH  = 16;
constexpr int D   = 128;
constexpr int M   = B * S;     // 4096
constexpr int H3  = 3 * H;     // 6144
constexpr float SM_SCALE = 0.08838834764831845f;  // 1/sqrt(128)

// ---------------------------------------------------------------------------
// Scratch
// ---------------------------------------------------------------------------
__device__ float g_qkv[(size_t)M * H3];      // [4096, 6144]
__device__ float g_ctx[(size_t)M * H];       // [4096, 2048] (tf32-rounded)
__device__ float g_atf[(size_t)M * H];       // hidden, tf32-rounded
__device__ float g_wqkvt[(size_t)H3 * H];    // W_qkv^T [6144][2048], tf32
__device__ float g_woutt[(size_t)H * H];     // W_out^T [2048][2048], tf32

// ---------------------------------------------------------------------------
// Helpers (baseline PTX only — compiles at compute_100)
// ---------------------------------------------------------------------------
__device__ __forceinline__ uint32_t smem_u32(const void* p) {
    uint32_t a;
    asm("{ .reg .u64 t; cvta.to.shared.u64 t, %1; cvt.u32.u64 %0, t; }"
        : "=r"(a) : "l"(p));
    return a;
}
__device__ __forceinline__ float f2tf(float x) {
    uint32_t r;
    asm("cvt.rna.tf32.f32 %0, %1;" : "=r"(r) : "f"(x));
    return __uint_as_float(r);
}
__device__ __forceinline__ void mma8u(float* d, const uint32_t* a, const uint32_t* b) {
    asm volatile(
        "mma.sync.aligned.m16n8k8.row.col.f32.tf32.tf32.f32 "
        "{%0,%1,%2,%3}, {%4,%5,%6,%7}, {%8,%9}, {%0,%1,%2,%3};\n"
        : "+f"(d[0]), "+f"(d[1]), "+f"(d[2]), "+f"(d[3])
        : "r"(a[0]), "r"(a[1]), "r"(a[2]), "r"(a[3]), "r"(b[0]), "r"(b[1]));
}
__device__ __forceinline__ void ldm_x4(uint32_t* r, uint32_t addr) {
    asm volatile("ldmatrix.sync.aligned.m8n8.x4.shared.b16 {%0,%1,%2,%3}, [%4];"
                 : "=r"(r[0]), "=r"(r[1]), "=r"(r[2]), "=r"(r[3]) : "r"(addr));
}
__device__ __forceinline__ void cp_async16(void* smem, const void* gmem) {
    uint32_t s = (uint32_t)__cvta_generic_to_shared(smem);
    asm volatile("cp.async.cg.shared.global [%0], [%1], 16;\n" :: "r"(s), "l"(gmem));
}
__device__ __forceinline__ void cp_commit() { asm volatile("cp.async.commit_group;\n"); }
template <int N>
__device__ __forceinline__ void cp_wait() {
    asm volatile("cp.async.wait_group %0;\n" :: "n"(N));
}

// ---------------------------------------------------------------------------
// Prologue 1: elementwise tf32 rounding (hidden -> g_atf)
// ---------------------------------------------------------------------------
__global__ void round_tf32_kernel(const float* __restrict__ in,
                                  float* __restrict__ out, int n4)
{
    int i = blockIdx.x * 256 + threadIdx.x;
    if (i < n4) {
        float4 v = reinterpret_cast<const float4*>(in)[i];
        v.x = f2tf(v.x); v.y = f2tf(v.y); v.z = f2tf(v.z); v.w = f2tf(v.w);
        reinterpret_cast<float4*>(out)[i] = v;
    }
}

// ---------------------------------------------------------------------------
// Prologue 2: W [K][N] -> Wt [N][K], tf32-rounded.  block (32,8)
// ---------------------------------------------------------------------------
__global__ void transpose_round_kernel(const float* __restrict__ W,
                                       float* __restrict__ Wt, int K, int N)
{
    __shared__ float t[32][33];
    const int n0 = blockIdx.x * 32, k0 = blockIdx.y * 32;
    const int tx = threadIdx.x, ty = threadIdx.y;
#pragma unroll
    for (int j = 0; j < 4; j++)
        t[ty + 8 * j][tx] = W[(size_t)(k0 + ty + 8 * j) * N + n0 + tx];
    __syncthreads();
#pragma unroll
    for (int j = 0; j < 4; j++)
        Wt[(size_t)(n0 + ty + 8 * j) * K + k0 + tx] = f2tf(t[tx][ty + 8 * j]);
}

// ---------------------------------------------------------------------------
// GEMM (round-10 verified): C = A @ Bt^T + bias. 2-stage cp.async, ldmatrix.
// ---------------------------------------------------------------------------
constexpr int APAD = 36;
constexpr int GA   = 128 * APAD;
constexpr int GSTG = 2 * GA;
constexpr int GSMEM_BYTES = 2 * GSTG * 4;   // 73728 B

__global__ __launch_bounds__(128, 3)
void gemm_ldm_kernel(const float* __restrict__ A,  int lda,
                     const float* __restrict__ Bt, int ldbt,
                     float* __restrict__ C,        int ldc,
                     int K, const float* __restrict__ bias)
{
    extern __shared__ __align__(16) float sg[];

    const int tid  = threadIdx.x;
    const int warp = tid >> 5, lane = tid & 31;
    const int wm = (warp >> 1) * 64, wn = (warp & 1) * 64;
    const int m0 = blockIdx.y * 128, n0 = blockIdx.x * 128;

    A  += (size_t)m0 * lda;
    Bt += (size_t)n0 * ldbt;
    C  += (size_t)m0 * ldc + n0;

    const int rowA = (lane & 7) + (lane & 8);
    const int colA = (lane & 16) ? 4 : 0;
    const int rowB = (lane & 7) + ((lane & 16) >> 1);
    const int colB = (lane & 8) ? 4 : 0;

    float acc[4][8][4];
#pragma unroll
    for (int mi = 0; mi < 4; mi++)
#pragma unroll
        for (int nj = 0; nj < 8; nj++)
#pragma unroll
            for (int r = 0; r < 4; r++) acc[mi][nj][r] = 0.0f;

    auto stage = [&](int kt, int buf) {
        float* dA = sg + buf * GSTG;
        float* dB = dA + GA;
        const int k0 = kt * 32;
#pragma unroll
        for (int j = 0; j < 8; j++) {
            int idx = tid + j * 128;
            int r = idx >> 3, c = (idx & 7) * 4;
            cp_async16(&dA[r * APAD + c], A + (size_t)r * lda + k0 + c);
        }
#pragma unroll
        for (int j = 0; j < 8; j++) {
            int idx = tid + j * 128;
            int r = idx >> 3, c = (idx & 7) * 4;
            cp_async16(&dB[r * APAD + c], Bt + (size_t)r * ldbt + k0 + c);
        }
        cp_commit();
    };

    stage(0, 0);
    const int KT = K / 32;

    for (int kt = 0; kt < KT; kt++) {
        const int buf = kt & 1;
        if (kt + 1 < KT) { stage(kt + 1, buf ^ 1); cp_wait<1>(); }
        else             { cp_wait<0>(); }
        __syncthreads();

        const float* cA = sg + buf * GSTG;
        const float* cB = cA + GA;
        uint32_t aAdr[4], bAdr[4];
#pragma unroll
        for (int mi = 0; mi < 4; mi++)
            aAdr[mi] = smem_u32(cA + (wm + mi * 16 + rowA) * APAD + colA);
#pragma unroll
        for (int njp = 0; njp < 4; njp++)
            bAdr[njp] = smem_u32(cB + (wn + njp * 16 + rowB) * APAD + colB);

#pragma unroll
        for (int kk = 0; kk < 32; kk += 8) {
            uint32_t a[4][4], bfr[4][4];
#pragma unroll
            for (int mi = 0; mi < 4; mi++)   ldm_x4(a[mi],   aAdr[mi]  + kk * 4);
#pragma unroll
            for (int njp = 0; njp < 4; njp++) ldm_x4(bfr[njp], bAdr[njp] + kk * 4);
#pragma unroll
            for (int mi = 0; mi < 4; mi++)
#pragma unroll
                for (int nj = 0; nj < 8; nj++)
                    mma8u(acc[mi][nj], a[mi], &bfr[nj >> 1][(nj & 1) * 2]);
        }
        __syncthreads();
    }

#pragma unroll
    for (int mi = 0; mi < 4; mi++) {
#pragma unroll
        for (int nj = 0; nj < 8; nj++) {
            const int g = lane >> 2, t = lane & 3;
            const int row = wm + mi * 16 + g;
            const int col = wn + nj * 8 + 2 * t;
            const float b0 = bias ? bias[n0 + col]     : 0.0f;
            const float b1 = bias ? bias[n0 + col + 1] : 0.0f;
            *reinterpret_cast<float2*>(C + (size_t)row * ldc + col) =
                make_float2(acc[mi][nj][0] + b0, acc[mi][nj][1] + b1);
            *reinterpret_cast<float2*>(C + (size_t)(row + 8) * ldc + col) =
                make_float2(acc[mi][nj][2] + b0, acc[mi][nj][3] + b1);
        }
    }
}

// ---------------------------------------------------------------------------
// Fused flash attention.
//  - Q/P A-fragments + K B-fragments via ldmatrix (stride 132 = 4 mod 32,
//    conflict-free; identical lane maps verified in the GEMM & round 9).
//  - V staging and V B-pattern scalar reads: byte-identical to the verified
//    round-8/10 path (VSTR 136, banks 8t+g, conflict-free).
// ---------------------------------------------------------------------------
constexpr int QP = 132, KSTR = 132, VSTR = 136, PP = 132;
constexpr int FLASH_SMEM_FLOATS = 128 * QP + 128 * VSTR + 128 * PP + 128 + S;
constexpr int FLASH_SMEM_BYTES  = FLASH_SMEM_FLOATS * 4;

__global__ __launch_bounds__(256)
void flash_mma_kernel(const float* __restrict__ mask)
{
    extern __shared__ __align__(16) float sm[];
    float* sQ    = sm;
    float* sKV   = sQ  + 128 * QP;
    float* sP    = sKV + 128 * VSTR;
    float* sRow  = sP  + 128 * PP;
    float* sMask = sRow + 128;

    const int tid  = threadIdx.x;
    const int warp = tid >> 5, lane = tid & 31;
    const int g = lane >> 2, t = lane & 3;
    const int wm = (warp >> 2) * 64, wn = (warp & 3) * 32;

    const int rowA = (lane & 7) + (lane & 8);
    const int colA = (lane & 16) ? 4 : 0;
    const int rowB = (lane & 7) + ((lane & 16) >> 1);
    const int colB = (lane & 8) ? 4 : 0;

    const int z  = blockIdx.y;
    const int b  = z >> 4;
    const int h  = z & 15;
    const int q0 = blockIdx.x * 128;

    const float* __restrict__ Qg = g_qkv + (size_t)(b * S + q0) * H3 + h * D;

#pragma unroll
    for (int i = tid; i < 4096; i += 256) {
        int r = i >> 5, c = (i & 31) * 4;
        float4 v = *reinterpret_cast<const float4*>(Qg + (size_t)r * H3 + c);
        v.x = f2tf(v.x); v.y = f2tf(v.y); v.z = f2tf(v.z); v.w = f2tf(v.w);
        *reinterpret_cast<float4*>(&sQ[r * QP + c]) = v;
    }
#pragma unroll
    for (int i = tid; i < S; i += 256) sMask[i] = mask[(size_t)b * S + i];
    if (tid < 128) sRow[tid] = 0.0f;

    // fixed ldmatrix base addresses
    uint32_t aQAdr[4], aPAdr[4], bKAdr[2];
#pragma unroll
    for (int mi = 0; mi < 4; mi++) {
        aQAdr[mi] = smem_u32(sQ + (wm + mi * 16 + rowA) * QP + colA);
        aPAdr[mi] = smem_u32(sP + (wm + mi * 16 + rowA) * PP + colA);
    }
#pragma unroll
    for (int njp = 0; njp < 2; njp++)
        bKAdr[njp] = smem_u32(sKV + (wn + njp * 16 + rowB) * KSTR + colB);

    const uint32_t* sKVu = reinterpret_cast<const uint32_t*>(sKV);

    float oacc[4][4][4];
#pragma unroll
    for (int mi = 0; mi < 4; mi++)
#pragma unroll
        for (int nj = 0; nj < 4; nj++)
#pragma unroll
            for (int r = 0; r < 4; r++) oacc[mi][nj][r] = 0.0f;

    for (int jt = 0; jt < S / 128; jt++) {
        const int n0 = jt * 128;
        const float* __restrict__ Kg = g_qkv + (size_t)(b * S + n0) * H3 + H     + h * D;
        const float* __restrict__ Vg = g_qkv + (size_t)(b * S + n0) * H3 + 2 * H + h * D;

        // ---- stage K [key][d], stride 132, tf32 ----
#pragma unroll
        for (int i = tid; i < 4096; i += 256) {
            int r = i >> 5, c = (i & 31) * 4;
            float4 v = *reinterpret_cast<const float4*>(Kg + (size_t)r * H3 + c);
            v.x = f2tf(v.x); v.y = f2tf(v.y); v.z = f2tf(v.z); v.w = f2tf(v.w);
            *reinterpret_cast<float4*>(&sKV[r * KSTR + c]) = v;
        }
        __syncthreads();

        // ---- S = Q @ K^T (full ldmatrix) ----
        float sacc[4][4][4];
#pragma unroll
        for (int mi = 0; mi < 4; mi++)
#pragma unroll
            for (int nj = 0; nj < 4; nj++)
#pragma unroll
                for (int r = 0; r < 4; r++) sacc[mi][nj][r] = 0.0f;

#pragma unroll
        for (int kk = 0; kk < D; kk += 8) {
            uint32_t a[4][4], bfr[2][4];
#pragma unroll
            for (int mi = 0; mi < 4; mi++)   ldm_x4(a[mi],   aQAdr[mi] + kk * 4);
#pragma unroll
            for (int njp = 0; njp < 2; njp++) ldm_x4(bfr[njp], bKAdr[njp] + kk * 4);
#pragma unroll
            for (int mi = 0; mi < 4; mi++)
#pragma unroll
                for (int nj = 0; nj < 4; nj++)
                    mma8u(sacc[mi][nj], a[mi], &bfr[nj >> 1][(nj & 1) * 2]);
        }
        __syncthreads();   // done reading K -> sKV reusable for V

        // ---- stage V [key][d], stride 136 (verified round-8 path) ----
#pragma unroll
        for (int i = tid; i < 4096; i += 256) {
            int r = i >> 5, c = (i & 31) * 4;
            float4 v = *reinterpret_cast<const float4*>(Vg + (size_t)r * H3 + c);
            v.x = f2tf(v.x); v.y = f2tf(v.y); v.z = f2tf(v.z); v.w = f2tf(v.w);
            *reinterpret_cast<float4*>(&sKV[r * VSTR + c]) = v;
        }

        // ---- P = exp(S*scale + mask); store tf32 P; rowsums ----
#pragma unroll
        for (int mi = 0; mi < 4; mi++) {
            const int r0 = wm + mi * 16 + g;
            float rp0 = 0.0f, rp1 = 0.0f;
#pragma unroll
            for (int nj = 0; nj < 4; nj++) {
                const int col = wn + nj * 8 + 2 * t;
                const float m0v = sMask[n0 + col];
                const float m1v = sMask[n0 + col + 1];
                float p00 = __expf(fmaf(sacc[mi][nj][0], SM_SCALE, m0v));
                float p01 = __expf(fmaf(sacc[mi][nj][1], SM_SCALE, m1v));
                float p10 = __expf(fmaf(sacc[mi][nj][2], SM_SCALE, m0v));
                float p11 = __expf(fmaf(sacc[mi][nj][3], SM_SCALE, m1v));
                rp0 += p00 + p01;
                rp1 += p10 + p11;
                *reinterpret_cast<float2*>(&sP[r0 * PP + col]) =
                    make_float2(f2tf(p00), f2tf(p01));
                *reinterpret_cast<float2*>(&sP[(r0 + 8) * PP + col]) =
                    make_float2(f2tf(p10), f2tf(p11));
            }
            rp0 += __shfl_xor_sync(0xffffffffu, rp0, 1);
            rp0 += __shfl_xor_sync(0xffffffffu, rp0, 2);
            rp1 += __shfl_xor_sync(0xffffffffu, rp1, 1);
            rp1 += __shfl_xor_sync(0xffffffffu, rp1, 2);
            if (t == 0) {
                atomicAdd(&sRow[r0], rp0);
                atomicAdd(&sRow[r0 + 8], rp1);
            }
        }
        __syncthreads();   // P + V visible

        // ---- O += P @ V : ldmatrix for P, scalar B-pattern for V ----
#pragma unroll
        for (int kk = 0; kk < 128; kk += 8) {
            uint32_t a[4][4], bf[4][2];
#pragma unroll
            for (int mi = 0; mi < 4; mi++) ldm_x4(a[mi], aPAdr[mi] + kk * 4);
#pragma unroll
            for (int nj = 0; nj < 4; nj++) {
                const int col = wn + nj * 8 + g;
                bf[nj][0] = sKVu[(kk + t) * VSTR + col];
                bf[nj][1] = sKVu[(kk + t + 4) * VSTR + col];
            }
#pragma unroll
            for (int mi = 0; mi < 4; mi++)
#pragma unroll
                for (int nj = 0; nj < 4; nj++)
                    mma8u(oacc[mi][nj], a[mi], bf[nj]);
        }
        __syncthreads();   // before next jt restages sKV / sP
    }

    // ---- epilogue: normalize, store ctx tf32-rounded ----
#pragma unroll
    for (int mi = 0; mi < 4; mi++) {
        const int r0 = wm + mi * 16 + g;
        const float inv0 = 1.0f / sRow[r0];
        const float inv1 = 1.0f / sRow[r0 + 8];
#pragma unroll
        for (int nj = 0; nj < 4; nj++) {
            const int col = wn + nj * 8 + 2 * t;
            float* dst = g_ctx + (size_t)(b * S + q0 + r0) * H + h * D + col;
            *reinterpret_cast<float2*>(dst) =
                make_float2(f2tf(oacc[mi][nj][0] * inv0), f2tf(oacc[mi][nj][1] * inv0));
            *reinterpret_cast<float2*>(dst + (size_t)8 * H) =
                make_float2(f2tf(oacc[mi][nj][2] * inv1), f2tf(oacc[mi][nj][3] * inv1));
        }
    }
}

// ---------------------------------------------------------------------------
// Launch
// ---------------------------------------------------------------------------
extern "C" void kernel_launch(void* const* d_in, const int* in_sizes, int n_in,
                              void* d_out, int out_size)
{
    const float* hidden = nullptr;
    const float* mask   = nullptr;
    const float* W_qkv  = nullptr;
    const float* b_qkv  = nullptr;
    const float* W_out  = nullptr;
    const float* b_out  = nullptr;

    for (int i = 0; i < n_in; i++) {
        switch (in_sizes[i]) {
            case 8388608:  hidden = (const float*)d_in[i]; break;
            case 4096:     mask   = (const float*)d_in[i]; break;
            case 12582912: W_qkv  = (const float*)d_in[i]; break;
            case 6144:     b_qkv  = (const float*)d_in[i]; break;
            case 4194304:  W_out  = (const float*)d_in[i]; break;
            case 2048:     b_out  = (const float*)d_in[i]; break;
            default: break;
        }
    }
    float* out = (float*)d_out;

    cudaFuncSetAttribute(flash_mma_kernel,
                         cudaFuncAttributeMaxDynamicSharedMemorySize,
                         FLASH_SMEM_BYTES);
    cudaFuncSetAttribute(gemm_ldm_kernel,
                         cudaFuncAttributeMaxDynamicSharedMemorySize,
                         GSMEM_BYTES);

    float* qkv_ptr;   cudaGetSymbolAddress((void**)&qkv_ptr,  g_qkv);
    float* ctx_ptr;   cudaGetSymbolAddress((void**)&ctx_ptr,  g_ctx);
    float* atf_ptr;   cudaGetSymbolAddress((void**)&atf_ptr,  g_atf);
    float* wqkvt_ptr; cudaGetSymbolAddress((void**)&wqkvt_ptr, g_wqkvt);
    float* woutt_ptr; cudaGetSymbolAddress((void**)&woutt_ptr, g_woutt);

    round_tf32_kernel<<<(M * H / 4 + 255) / 256, 256>>>(hidden, atf_ptr, M * H / 4);
    transpose_round_kernel<<<dim3(H3 / 32, H / 32), dim3(32, 8)>>>(W_qkv, wqkvt_ptr, H, H3);
    transpose_round_kernel<<<dim3(H / 32, H / 32), dim3(32, 8)>>>(W_out, woutt_ptr, H, H);

    gemm_ldm_kernel<<<dim3(H3 / 128, M / 128), 128, GSMEM_BYTES>>>(
        atf_ptr, H, wqkvt_ptr, H, qkv_ptr, H3, H, b_qkv);

    flash_mma_kernel<<<dim3(S / 128, B * NH), 256, FLASH_SMEM_BYTES>>>(mask);

    gemm_ldm_kernel<<<dim3(H / 128, M / 128), 128, GSMEM_BYTES>>>(
        ctx_ptr, H, woutt_ptr, H, out, H, H, b_out);
}

// round 12
// speedup vs baseline: 1.1062x; 1.1062x over previous
#include <cuda_runtime.h>
#include <cstdint>

// ---------------------------------------------------------------------------
// Problem constants
// ---------------------------------------------------------------------------
constexpr int B   = 2;
constexpr int S   = 2048;
constexpr int H   = 2048;
constexpr int NH  = 16;
constexpr int D   = 128;
constexpr int M   = B * S;     // 4096
constexpr int H3  = 3 * H;     // 6144
constexpr float SM_SCALE = 0.08838834764831845f;  // 1/sqrt(128)

// ---------------------------------------------------------------------------
// Scratch
// ---------------------------------------------------------------------------
__device__ float g_qkv[(size_t)M * H3];      // [4096, 6144] tf32-rounded
__device__ float g_ctx[(size_t)M * H];       // [4096, 2048] tf32-rounded
__device__ float g_atf[(size_t)M * H];       // hidden, tf32-rounded
__device__ float g_wqkvt[(size_t)H3 * H];    // W_qkv^T, tf32
__device__ float g_woutt[(size_t)H * H];     // W_out^T, tf32

// ---------------------------------------------------------------------------
// Helpers (baseline PTX only — compiles at compute_100)
// ---------------------------------------------------------------------------
__device__ __forceinline__ uint32_t smem_u32(const void* p) {
    uint32_t a;
    asm("{ .reg .u64 t; cvta.to.shared.u64 t, %1; cvt.u32.u64 %0, t; }"
        : "=r"(a) : "l"(p));
    return a;
}
__device__ __forceinline__ float f2tf(float x) {
    uint32_t r;
    asm("cvt.rna.tf32.f32 %0, %1;" : "=r"(r) : "f"(x));
    return __uint_as_float(r);
}
__device__ __forceinline__ void mma8u(float* d, const uint32_t* a, const uint32_t* b) {
    asm volatile(
        "mma.sync.aligned.m16n8k8.row.col.f32.tf32.tf32.f32 "
        "{%0,%1,%2,%3}, {%4,%5,%6,%7}, {%8,%9}, {%0,%1,%2,%3};\n"
        : "+f"(d[0]), "+f"(d[1]), "+f"(d[2]), "+f"(d[3])
        : "r"(a[0]), "r"(a[1]), "r"(a[2]), "r"(a[3]), "r"(b[0]), "r"(b[1]));
}
__device__ __forceinline__ void ldm_x4(uint32_t* r, uint32_t addr) {
    asm volatile("ldmatrix.sync.aligned.m8n8.x4.shared.b16 {%0,%1,%2,%3}, [%4];"
                 : "=r"(r[0]), "=r"(r[1]), "=r"(r[2]), "=r"(r[3]) : "r"(addr));
}
__device__ __forceinline__ void cp_async16(void* smem, const void* gmem) {
    uint32_t s = (uint32_t)__cvta_generic_to_shared(smem);
    asm volatile("cp.async.cg.shared.global [%0], [%1], 16;\n" :: "r"(s), "l"(gmem));
}
__device__ __forceinline__ void cp_commit() { asm volatile("cp.async.commit_group;\n"); }
template <int N>
__device__ __forceinline__ void cp_wait() {
    asm volatile("cp.async.wait_group %0;\n" :: "n"(N));
}

// ---------------------------------------------------------------------------
// Prologue 1: elementwise tf32 rounding (hidden -> g_atf)
// ---------------------------------------------------------------------------
__global__ void round_tf32_kernel(const float* __restrict__ in,
                                  float* __restrict__ out, int n4)
{
    int i = blockIdx.x * 256 + threadIdx.x;
    if (i < n4) {
        float4 v = reinterpret_cast<const float4*>(in)[i];
        v.x = f2tf(v.x); v.y = f2tf(v.y); v.z = f2tf(v.z); v.w = f2tf(v.w);
        reinterpret_cast<float4*>(out)[i] = v;
    }
}

// ---------------------------------------------------------------------------
// Prologue 2: W [K][N] -> Wt [N][K], tf32-rounded.  block (32,8)
// ---------------------------------------------------------------------------
__global__ void transpose_round_kernel(const float* __restrict__ W,
                                       float* __restrict__ Wt, int K, int N)
{
    __shared__ float t[32][33];
    const int n0 = blockIdx.x * 32, k0 = blockIdx.y * 32;
    const int tx = threadIdx.x, ty = threadIdx.y;
#pragma unroll
    for (int j = 0; j < 4; j++)
        t[ty + 8 * j][tx] = W[(size_t)(k0 + ty + 8 * j) * N + n0 + tx];
    __syncthreads();
#pragma unroll
    for (int j = 0; j < 4; j++)
        Wt[(size_t)(n0 + ty + 8 * j) * K + k0 + tx] = f2tf(t[tx][ty + 8 * j]);
}

// ---------------------------------------------------------------------------
// GEMM (round-10 verified): C = A @ Bt^T + bias. 2-stage cp.async, ldmatrix.
// round_out != 0 -> store tf32-rounded C (used for QKV; NOT for final output).
// ---------------------------------------------------------------------------
constexpr int APAD = 36;
constexpr int GA   = 128 * APAD;
constexpr int GSTG = 2 * GA;
constexpr int GSMEM_BYTES = 2 * GSTG * 4;   // 73728 B

__global__ __launch_bounds__(128, 3)
void gemm_ldm_kernel(const float* __restrict__ A,  int lda,
                     const float* __restrict__ Bt, int ldbt,
                     float* __restrict__ C,        int ldc,
                     int K, const float* __restrict__ bias, int round_out)
{
    extern __shared__ __align__(16) float sg[];

    const int tid  = threadIdx.x;
    const int warp = tid >> 5, lane = tid & 31;
    const int wm = (warp >> 1) * 64, wn = (warp & 1) * 64;
    const int m0 = blockIdx.y * 128, n0 = blockIdx.x * 128;

    A  += (size_t)m0 * lda;
    Bt += (size_t)n0 * ldbt;
    C  += (size_t)m0 * ldc + n0;

    const int rowA = (lane & 7) + (lane & 8);
    const int colA = (lane & 16) ? 4 : 0;
    const int rowB = (lane & 7) + ((lane & 16) >> 1);
    const int colB = (lane & 8) ? 4 : 0;

    float acc[4][8][4];
#pragma unroll
    for (int mi = 0; mi < 4; mi++)
#pragma unroll
        for (int nj = 0; nj < 8; nj++)
#pragma unroll
            for (int r = 0; r < 4; r++) acc[mi][nj][r] = 0.0f;

    auto stage = [&](int kt, int buf) {
        float* dA = sg + buf * GSTG;
        float* dB = dA + GA;
        const int k0 = kt * 32;
#pragma unroll
        for (int j = 0; j < 8; j++) {
            int idx = tid + j * 128;
            int r = idx >> 3, c = (idx & 7) * 4;
            cp_async16(&dA[r * APAD + c], A + (size_t)r * lda + k0 + c);
        }
#pragma unroll
        for (int j = 0; j < 8; j++) {
            int idx = tid + j * 128;
            int r = idx >> 3, c = (idx & 7) * 4;
            cp_async16(&dB[r * APAD + c], Bt + (size_t)r * ldbt + k0 + c);
        }
        cp_commit();
    };

    stage(0, 0);
    const int KT = K / 32;

    for (int kt = 0; kt < KT; kt++) {
        const int buf = kt & 1;
        if (kt + 1 < KT) { stage(kt + 1, buf ^ 1); cp_wait<1>(); }
        else             { cp_wait<0>(); }
        __syncthreads();

        const float* cA = sg + buf * GSTG;
        const float* cB = cA + GA;
        uint32_t aAdr[4], bAdr[4];
#pragma unroll
        for (int mi = 0; mi < 4; mi++)
            aAdr[mi] = smem_u32(cA + (wm + mi * 16 + rowA) * APAD + colA);
#pragma unroll
        for (int njp = 0; njp < 4; njp++)
            bAdr[njp] = smem_u32(cB + (wn + njp * 16 + rowB) * APAD + colB);

#pragma unroll
        for (int kk = 0; kk < 32; kk += 8) {
            uint32_t a[4][4], bfr[4][4];
#pragma unroll
            for (int mi = 0; mi < 4; mi++)   ldm_x4(a[mi],   aAdr[mi]  + kk * 4);
#pragma unroll
            for (int njp = 0; njp < 4; njp++) ldm_x4(bfr[njp], bAdr[njp] + kk * 4);
#pragma unroll
            for (int mi = 0; mi < 4; mi++)
#pragma unroll
                for (int nj = 0; nj < 8; nj++)
                    mma8u(acc[mi][nj], a[mi], &bfr[nj >> 1][(nj & 1) * 2]);
        }
        __syncthreads();
    }

#pragma unroll
    for (int mi = 0; mi < 4; mi++) {
#pragma unroll
        for (int nj = 0; nj < 8; nj++) {
            const int g = lane >> 2, t = lane & 3;
            const int row = wm + mi * 16 + g;
            const int col = wn + nj * 8 + 2 * t;
            const float b0 = bias ? bias[n0 + col]     : 0.0f;
            const float b1 = bias ? bias[n0 + col + 1] : 0.0f;
            float v0 = acc[mi][nj][0] + b0, v1 = acc[mi][nj][1] + b1;
            float v2 = acc[mi][nj][2] + b0, v3 = acc[mi][nj][3] + b1;
            if (round_out) { v0 = f2tf(v0); v1 = f2tf(v1); v2 = f2tf(v2); v3 = f2tf(v3); }
            *reinterpret_cast<float2*>(C + (size_t)row * ldc + col) = make_float2(v0, v1);
            *reinterpret_cast<float2*>(C + (size_t)(row + 8) * ldc + col) = make_float2(v2, v3);
        }
    }
}

// ---------------------------------------------------------------------------
// Fused flash attention, cp.async software-pipelined.
// 64-query tile, 128-key tiles. Q/K/V already tf32-rounded in g_qkv.
// Buffers: sQ[64][132], sK[128][132], sV[128][136], sP[64][132]  (~208 KB)
// Per jt: wait K -> sync -> async V -> QK -> exp->P -> wait V -> sync
//         -> async K[jt+1] -> PV.   (2 barriers, loads hidden)
// ---------------------------------------------------------------------------
constexpr int FQ  = 64;
constexpr int QP  = 132, KP = 132, VP = 136, PP = 132;
constexpr int FLASH_SMEM_FLOATS =
    FQ * QP + 128 * KP + 128 * VP + FQ * PP + FQ + S;
constexpr int FLASH_SMEM_BYTES = FLASH_SMEM_FLOATS * 4;   // ~213 KB

__global__ __launch_bounds__(256)
void flash_mma_kernel(const float* __restrict__ mask)
{
    extern __shared__ __align__(16) float sm[];
    float* sQ    = sm;                       // [64][132]
    float* sK    = sQ + FQ * QP;             // [128][132]
    float* sV    = sK + 128 * KP;            // [128][136]
    float* sP    = sV + 128 * VP;            // [64][132]
    float* sRow  = sP + FQ * PP;             // [64]
    float* sMask = sRow + FQ;                // [2048]

    const int tid  = threadIdx.x;
    const int warp = tid >> 5, lane = tid & 31;
    const int g = lane >> 2, t = lane & 3;
    const int wm = (warp >> 2) * 32;         // 2 row-groups of 32 q
    const int wn = (warp & 3) * 32;          // 4 col-groups of 32

    const int rowA = (lane & 7) + (lane & 8);
    const int colA = (lane & 16) ? 4 : 0;
    const int rowB = (lane & 7) + ((lane & 16) >> 1);
    const int colB = (lane & 8) ? 4 : 0;

    const int z  = blockIdx.y;
    const int b  = z >> 4;
    const int h  = z & 15;
    const int q0 = blockIdx.x * FQ;

    const float* __restrict__ Qg = g_qkv + (size_t)(b * S + q0) * H3 + h * D;

    // ---- prologue: async Q + K0 (one group), mask, rowsums ----
#pragma unroll
    for (int j = 0; j < 8; j++) {            // Q: 2048 float4
        int idx = tid + j * 256;
        int r = idx >> 5, c = (idx & 31) * 4;
        cp_async16(&sQ[r * QP + c], Qg + (size_t)r * H3 + c);
    }
    {
        const float* Kg0 = g_qkv + (size_t)(b * S) * H3 + H + h * D;
#pragma unroll
        for (int j = 0; j < 16; j++) {       // K: 4096 float4
            int idx = tid + j * 256;
            int r = idx >> 5, c = (idx & 31) * 4;
            cp_async16(&sK[r * KP + c], Kg0 + (size_t)r * H3 + c);
        }
    }
    cp_commit();
#pragma unroll
    for (int i = tid; i < S; i += 256) sMask[i] = mask[(size_t)b * S + i];
    if (tid < FQ) sRow[tid] = 0.0f;

    // fixed ldmatrix addresses
    uint32_t aQAdr[2], aPAdr[2], bKAdr[2];
#pragma unroll
    for (int mi = 0; mi < 2; mi++) {
        aQAdr[mi] = smem_u32(sQ + (wm + mi * 16 + rowA) * QP + colA);
        aPAdr[mi] = smem_u32(sP + (wm + mi * 16 + rowA) * PP + colA);
    }
#pragma unroll
    for (int njp = 0; njp < 2; njp++)
        bKAdr[njp] = smem_u32(sK + (wn + njp * 16 + rowB) * KP + colB);

    const uint32_t* sVu = reinterpret_cast<const uint32_t*>(sV);

    float oacc[2][4][4];
#pragma unroll
    for (int mi = 0; mi < 2; mi++)
#pragma unroll
        for (int nj = 0; nj < 4; nj++)
#pragma unroll
            for (int r = 0; r < 4; r++) oacc[mi][nj][r] = 0.0f;

    for (int jt = 0; jt < S / 128; jt++) {
        const int n0 = jt * 128;

        cp_wait<0>();           // K[jt] (and any older groups) complete
        __syncthreads();        // all warps past PV[jt-1] (sV, sP reusable)

        // ---- prefetch V[jt] (overlaps QK) ----
        {
            const float* Vg = g_qkv + (size_t)(b * S + n0) * H3 + 2 * H + h * D;
#pragma unroll
            for (int j = 0; j < 16; j++) {
                int idx = tid + j * 256;
                int r = idx >> 5, c = (idx & 31) * 4;
                cp_async16(&sV[r * VP + c], Vg + (size_t)r * H3 + c);
            }
            cp_commit();
        }

        // ---- S = Q @ K^T ----
        float sacc[2][4][4];
#pragma unroll
        for (int mi = 0; mi < 2; mi++)
#pragma unroll
            for (int nj = 0; nj < 4; nj++)
#pragma unroll
                for (int r = 0; r < 4; r++) sacc[mi][nj][r] = 0.0f;

#pragma unroll
        for (int kk = 0; kk < D; kk += 8) {
            uint32_t a[2][4], bfr[2][4];
#pragma unroll
            for (int mi = 0; mi < 2; mi++)   ldm_x4(a[mi],   aQAdr[mi] + kk * 4);
#pragma unroll
            for (int njp = 0; njp < 2; njp++) ldm_x4(bfr[njp], bKAdr[njp] + kk * 4);
#pragma unroll
            for (int mi = 0; mi < 2; mi++)
#pragma unroll
                for (int nj = 0; nj < 4; nj++)
                    mma8u(sacc[mi][nj], a[mi], &bfr[nj >> 1][(nj & 1) * 2]);
        }

        // ---- P = exp(S*scale + mask) -> sP (own rows only); rowsums ----
#pragma unroll
        for (int mi = 0; mi < 2; mi++) {
            const int r0 = wm + mi * 16 + g;
            float rp0 = 0.0f, rp1 = 0.0f;
#pragma unroll
            for (int nj = 0; nj < 4; nj++) {
                const int col = wn + nj * 8 + 2 * t;
                const float m0v = sMask[n0 + col];
                const float m1v = sMask[n0 + col + 1];
                float p00 = __expf(fmaf(sacc[mi][nj][0], SM_SCALE, m0v));
                float p01 = __expf(fmaf(sacc[mi][nj][1], SM_SCALE, m1v));
                float p10 = __expf(fmaf(sacc[mi][nj][2], SM_SCALE, m0v));
                float p11 = __expf(fmaf(sacc[mi][nj][3], SM_SCALE, m1v));
                rp0 += p00 + p01;
                rp1 += p10 + p11;
                *reinterpret_cast<float2*>(&sP[r0 * PP + col]) =
                    make_float2(f2tf(p00), f2tf(p01));
                *reinterpret_cast<float2*>(&sP[(r0 + 8) * PP + col]) =
                    make_float2(f2tf(p10), f2tf(p11));
            }
            rp0 += __shfl_xor_sync(0xffffffffu, rp0, 1);
            rp0 += __shfl_xor_sync(0xffffffffu, rp0, 2);
            rp1 += __shfl_xor_sync(0xffffffffu, rp1, 1);
            rp1 += __shfl_xor_sync(0xffffffffu, rp1, 2);
            if (t == 0) {
                atomicAdd(&sRow[r0], rp0);
                atomicAdd(&sRow[r0 + 8], rp1);
            }
        }

        cp_wait<0>();           // V[jt] complete
        __syncthreads();        // all P visible; all warps past QK reads of sK

        // ---- prefetch K[jt+1] (overlaps PV) ----
        if (jt + 1 < S / 128) {
            const float* Kg = g_qkv + (size_t)(b * S + n0 + 128) * H3 + H + h * D;
#pragma unroll
            for (int j = 0; j < 16; j++) {
                int idx = tid + j * 256;
                int r = idx >> 5, c = (idx & 31) * 4;
                cp_async16(&sK[r * KP + c], Kg + (size_t)r * H3 + c);
            }
            cp_commit();
        }

        // ---- O += P @ V : ldmatrix P, scalar B-pattern V (stride 136) ----
#pragma unroll
        for (int kk = 0; kk < 128; kk += 8) {
            uint32_t a[2][4], bf[4][2];
#pragma unroll
            for (int mi = 0; mi < 2; mi++) ldm_x4(a[mi], aPAdr[mi] + kk * 4);
#pragma unroll
            for (int nj = 0; nj < 4; nj++) {
                const int col = wn + nj * 8 + g;
                bf[nj][0] = sVu[(kk + t) * VP + col];
                bf[nj][1] = sVu[(kk + t + 4) * VP + col];
            }
#pragma unroll
            for (int mi = 0; mi < 2; mi++)
#pragma unroll
                for (int nj = 0; nj < 4; nj++)
                    mma8u(oacc[mi][nj], a[mi], bf[nj]);
        }
    }

    // ---- epilogue: normalize, store ctx tf32-rounded ----
#pragma unroll
    for (int mi = 0; mi < 2; mi++) {
        const int r0 = wm + mi * 16 + g;
        const float inv0 = 1.0f / sRow[r0];
        const float inv1 = 1.0f / sRow[r0 + 8];
#pragma unroll
        for (int nj = 0; nj < 4; nj++) {
            const int col = wn + nj * 8 + 2 * t;
            float* dst = g_ctx + (size_t)(b * S + q0 + r0) * H + h * D + col;
            *reinterpret_cast<float2*>(dst) =
                make_float2(f2tf(oacc[mi][nj][0] * inv0), f2tf(oacc[mi][nj][1] * inv0));
            *reinterpret_cast<float2*>(dst + (size_t)8 * H) =
                make_float2(f2tf(oacc[mi][nj][2] * inv1), f2tf(oacc[mi][nj][3] * inv1));
        }
    }
}

// ---------------------------------------------------------------------------
// Launch
// ---------------------------------------------------------------------------
extern "C" void kernel_launch(void* const* d_in, const int* in_sizes, int n_in,
                              void* d_out, int out_size)
{
    const float* hidden = nullptr;
    const float* mask   = nullptr;
    const float* W_qkv  = nullptr;
    const float* b_qkv  = nullptr;
    const float* W_out  = nullptr;
    const float* b_out  = nullptr;

    for (int i = 0; i < n_in; i++) {
        switch (in_sizes[i]) {
            case 8388608:  hidden = (const float*)d_in[i]; break;
            case 4096:     mask   = (const float*)d_in[i]; break;
            case 12582912: W_qkv  = (const float*)d_in[i]; break;
            case 6144:     b_qkv  = (const float*)d_in[i]; break;
            case 4194304:  W_out  = (const float*)d_in[i]; break;
            case 2048:     b_out  = (const float*)d_in[i]; break;
            default: break;
        }
    }
    float* out = (float*)d_out;

    cudaFuncSetAttribute(flash_mma_kernel,
                         cudaFuncAttributeMaxDynamicSharedMemorySize,
                         FLASH_SMEM_BYTES);
    cudaFuncSetAttribute(gemm_ldm_kernel,
                         cudaFuncAttributeMaxDynamicSharedMemorySize,
                         GSMEM_BYTES);

    float* qkv_ptr;   cudaGetSymbolAddress((void**)&qkv_ptr,  g_qkv);
    float* ctx_ptr;   cudaGetSymbolAddress((void**)&ctx_ptr,  g_ctx);
    float* atf_ptr;   cudaGetSymbolAddress((void**)&atf_ptr,  g_atf);
    float* wqkvt_ptr; cudaGetSymbolAddress((void**)&wqkvt_ptr, g_wqkvt);
    float* woutt_ptr; cudaGetSymbolAddress((void**)&woutt_ptr, g_woutt);

    round_tf32_kernel<<<(M * H / 4 + 255) / 256, 256>>>(hidden, atf_ptr, M * H / 4);
    transpose_round_kernel<<<dim3(H3 / 32, H / 32), dim3(32, 8)>>>(W_qkv, wqkvt_ptr, H, H3);
    transpose_round_kernel<<<dim3(H / 32, H / 32), dim3(32, 8)>>>(W_out, woutt_ptr, H, H);

    // QKV projection (output tf32-rounded so flash can cp.async raw tiles)
    gemm_ldm_kernel<<<dim3(H3 / 128, M / 128), 128, GSMEM_BYTES>>>(
        atf_ptr, H, wqkvt_ptr, H, qkv_ptr, H3, H, b_qkv, 1);

    flash_mma_kernel<<<dim3(S / FQ, B * NH), 256, FLASH_SMEM_BYTES>>>(mask);

    // output projection (full fp32 output)
    gemm_ldm_kernel<<<dim3(H / 128, M / 128), 128, GSMEM_BYTES>>>(
        ctx_ptr, H, woutt_ptr, H, out, H, H, b_out, 0);
}

// round 13
// speedup vs baseline: 1.1341x; 1.0252x over previous
#include <cuda_runtime.h>
#include <cstdint>

// ---------------------------------------------------------------------------
// Problem constants
// ---------------------------------------------------------------------------
constexpr int B   = 2;
constexpr int S   = 2048;
constexpr int H   = 2048;
constexpr int NH  = 16;
constexpr int D   = 128;
constexpr int M   = B * S;     // 4096
constexpr int H3  = 3 * H;     // 6144
constexpr float SM_SCALE = 0.08838834764831845f;  // 1/sqrt(128)

// ---------------------------------------------------------------------------
// Scratch
// ---------------------------------------------------------------------------
__device__ float g_qkv[(size_t)M * H3];      // [4096, 6144] tf32-rounded
__device__ float g_ctx[(size_t)M * H];       // [4096, 2048] tf32-rounded
__device__ float g_atf[(size_t)M * H];       // hidden, tf32-rounded
__device__ float g_wqkvt[(size_t)H3 * H];    // W_qkv^T, tf32
__device__ float g_woutt[(size_t)H * H];     // W_out^T, tf32

// ---------------------------------------------------------------------------
// Helpers (baseline PTX only — compiles at compute_100)
// ---------------------------------------------------------------------------
__device__ __forceinline__ uint32_t smem_u32(const void* p) {
    uint32_t a;
    asm("{ .reg .u64 t; cvta.to.shared.u64 t, %1; cvt.u32.u64 %0, t; }"
        : "=r"(a) : "l"(p));
    return a;
}
__device__ __forceinline__ float f2tf(float x) {
    uint32_t r;
    asm("cvt.rna.tf32.f32 %0, %1;" : "=r"(r) : "f"(x));
    return __uint_as_float(r);
}
__device__ __forceinline__ void mma8u(float* d, const uint32_t* a, const uint32_t* b) {
    asm volatile(
        "mma.sync.aligned.m16n8k8.row.col.f32.tf32.tf32.f32 "
        "{%0,%1,%2,%3}, {%4,%5,%6,%7}, {%8,%9}, {%0,%1,%2,%3};\n"
        : "+f"(d[0]), "+f"(d[1]), "+f"(d[2]), "+f"(d[3])
        : "r"(a[0]), "r"(a[1]), "r"(a[2]), "r"(a[3]), "r"(b[0]), "r"(b[1]));
}
__device__ __forceinline__ void ldm_x4(uint32_t* r, uint32_t addr) {
    asm volatile("ldmatrix.sync.aligned.m8n8.x4.shared.b16 {%0,%1,%2,%3}, [%4];"
                 : "=r"(r[0]), "=r"(r[1]), "=r"(r[2]), "=r"(r[3]) : "r"(addr));
}
__device__ __forceinline__ void cp_async16(void* smem, const void* gmem) {
    uint32_t s = (uint32_t)__cvta_generic_to_shared(smem);
    asm volatile("cp.async.cg.shared.global [%0], [%1], 16;\n" :: "r"(s), "l"(gmem));
}
__device__ __forceinline__ void cp_commit() { asm volatile("cp.async.commit_group;\n"); }
template <int N>
__device__ __forceinline__ void cp_wait() {
    asm volatile("cp.async.wait_group %0;\n" :: "n"(N));
}

// ---------------------------------------------------------------------------
// Prologue 1: elementwise tf32 rounding (hidden -> g_atf)
// ---------------------------------------------------------------------------
__global__ void round_tf32_kernel(const float* __restrict__ in,
                                  float* __restrict__ out, int n4)
{
    int i = blockIdx.x * 256 + threadIdx.x;
    if (i < n4) {
        float4 v = reinterpret_cast<const float4*>(in)[i];
        v.x = f2tf(v.x); v.y = f2tf(v.y); v.z = f2tf(v.z); v.w = f2tf(v.w);
        reinterpret_cast<float4*>(out)[i] = v;
    }
}

// ---------------------------------------------------------------------------
// Prologue 2: W [K][N] -> Wt [N][K], tf32-rounded.  block (32,8)
// ---------------------------------------------------------------------------
__global__ void transpose_round_kernel(const float* __restrict__ W,
                                       float* __restrict__ Wt, int K, int N)
{
    __shared__ float t[32][33];
    const int n0 = blockIdx.x * 32, k0 = blockIdx.y * 32;
    const int tx = threadIdx.x, ty = threadIdx.y;
#pragma unroll
    for (int j = 0; j < 4; j++)
        t[ty + 8 * j][tx] = W[(size_t)(k0 + ty + 8 * j) * N + n0 + tx];
    __syncthreads();
#pragma unroll
    for (int j = 0; j < 4; j++)
        Wt[(size_t)(n0 + ty + 8 * j) * K + k0 + tx] = f2tf(t[tx][ty + 8 * j]);
}

// ---------------------------------------------------------------------------
// GEMM: C[128m x 64n per CTA] = A @ Bt^T + bias.  2-stage cp.async, ldmatrix.
// 4 warps, each 64x32.  __launch_bounds__(128,4): 4 CTAs/SM -> 4 warps/SMSP
// (regs 4*128*128=64K, smem 4*55296=221KB).  round_out -> tf32-rounded C.
// ---------------------------------------------------------------------------
constexpr int APAD = 36;
constexpr int GA   = 128 * APAD;            // A tile floats
constexpr int GB   = 64 * APAD;             // B tile floats
constexpr int GSTG = GA + GB;               // per stage (6912 floats)
constexpr int GSMEM_BYTES = 2 * GSTG * 4;   // 55296 B

__global__ __launch_bounds__(128, 4)
void gemm_ldm_kernel(const float* __restrict__ A,  int lda,
                     const float* __restrict__ Bt, int ldbt,
                     float* __restrict__ C,        int ldc,
                     int K, const float* __restrict__ bias, int round_out)
{
    extern __shared__ __align__(16) float sg[];

    const int tid  = threadIdx.x;
    const int warp = tid >> 5, lane = tid & 31;
    const int wm = (warp >> 1) * 64, wn = (warp & 1) * 32;
    const int m0 = blockIdx.y * 128, n0 = blockIdx.x * 64;

    A  += (size_t)m0 * lda;
    Bt += (size_t)n0 * ldbt;
    C  += (size_t)m0 * ldc + n0;

    const int rowA = (lane & 7) + (lane & 8);
    const int colA = (lane & 16) ? 4 : 0;
    const int rowB = (lane & 7) + ((lane & 16) >> 1);
    const int colB = (lane & 8) ? 4 : 0;

    float acc[4][4][4];
#pragma unroll
    for (int mi = 0; mi < 4; mi++)
#pragma unroll
        for (int nj = 0; nj < 4; nj++)
#pragma unroll
            for (int r = 0; r < 4; r++) acc[mi][nj][r] = 0.0f;

    auto stage = [&](int kt, int buf) {
        float* dA = sg + buf * GSTG;
        float* dB = dA + GA;
        const int k0 = kt * 32;
#pragma unroll
        for (int j = 0; j < 8; j++) {       // A: 1024 16B chunks / 128 thr
            int idx = tid + j * 128;
            int r = idx >> 3, c = (idx & 7) * 4;
            cp_async16(&dA[r * APAD + c], A + (size_t)r * lda + k0 + c);
        }
#pragma unroll
        for (int j = 0; j < 4; j++) {       // B: 512 16B chunks
            int idx = tid + j * 128;
            int r = idx >> 3, c = (idx & 7) * 4;
            cp_async16(&dB[r * APAD + c], Bt + (size_t)r * ldbt + k0 + c);
        }
        cp_commit();
    };

    stage(0, 0);
    const int KT = K / 32;

    for (int kt = 0; kt < KT; kt++) {
        const int buf = kt & 1;
        if (kt + 1 < KT) { stage(kt + 1, buf ^ 1); cp_wait<1>(); }
        else             { cp_wait<0>(); }
        __syncthreads();

        const float* cA = sg + buf * GSTG;
        const float* cB = cA + GA;
        uint32_t aAdr[4], bAdr[2];
#pragma unroll
        for (int mi = 0; mi < 4; mi++)
            aAdr[mi] = smem_u32(cA + (wm + mi * 16 + rowA) * APAD + colA);
#pragma unroll
        for (int njp = 0; njp < 2; njp++)
            bAdr[njp] = smem_u32(cB + (wn + njp * 16 + rowB) * APAD + colB);

#pragma unroll
        for (int kk = 0; kk < 32; kk += 8) {
            uint32_t a[4][4], bfr[2][4];
#pragma unroll
            for (int mi = 0; mi < 4; mi++)   ldm_x4(a[mi],   aAdr[mi]  + kk * 4);
#pragma unroll
            for (int njp = 0; njp < 2; njp++) ldm_x4(bfr[njp], bAdr[njp] + kk * 4);
#pragma unroll
            for (int mi = 0; mi < 4; mi++)
#pragma unroll
                for (int nj = 0; nj < 4; nj++)
                    mma8u(acc[mi][nj], a[mi], &bfr[nj >> 1][(nj & 1) * 2]);
        }
        __syncthreads();
    }

#pragma unroll
    for (int mi = 0; mi < 4; mi++) {
#pragma unroll
        for (int nj = 0; nj < 4; nj++) {
            const int g = lane >> 2, t = lane & 3;
            const int row = wm + mi * 16 + g;
            const int col = wn + nj * 8 + 2 * t;
            const float b0 = bias ? bias[n0 + col]     : 0.0f;
            const float b1 = bias ? bias[n0 + col + 1] : 0.0f;
            float v0 = acc[mi][nj][0] + b0, v1 = acc[mi][nj][1] + b1;
            float v2 = acc[mi][nj][2] + b0, v3 = acc[mi][nj][3] + b1;
            if (round_out) { v0 = f2tf(v0); v1 = f2tf(v1); v2 = f2tf(v2); v3 = f2tf(v3); }
            *reinterpret_cast<float2*>(C + (size_t)row * ldc + col) = make_float2(v0, v1);
            *reinterpret_cast<float2*>(C + (size_t)(row + 8) * ldc + col) = make_float2(v2, v3);
        }
    }
}

// ---------------------------------------------------------------------------
// Fused flash attention, cp.async software-pipelined (round-12 verified).
// ---------------------------------------------------------------------------
constexpr int FQ  = 64;
constexpr int QP  = 132, KP = 132, VP = 136, PP = 132;
constexpr int FLASH_SMEM_FLOATS =
    FQ * QP + 128 * KP + 128 * VP + FQ * PP + FQ + S;
constexpr int FLASH_SMEM_BYTES = FLASH_SMEM_FLOATS * 4;   // ~213 KB

__global__ __launch_bounds__(256)
void flash_mma_kernel(const float* __restrict__ mask)
{
    extern __shared__ __align__(16) float sm[];
    float* sQ    = sm;                       // [64][132]
    float* sK    = sQ + FQ * QP;             // [128][132]
    float* sV    = sK + 128 * KP;            // [128][136]
    float* sP    = sV + 128 * VP;            // [64][132]
    float* sRow  = sP + FQ * PP;             // [64]
    float* sMask = sRow + FQ;                // [2048]

    const int tid  = threadIdx.x;
    const int warp = tid >> 5, lane = tid & 31;
    const int g = lane >> 2, t = lane & 3;
    const int wm = (warp >> 2) * 32;
    const int wn = (warp & 3) * 32;

    const int rowA = (lane & 7) + (lane & 8);
    const int colA = (lane & 16) ? 4 : 0;
    const int rowB = (lane & 7) + ((lane & 16) >> 1);
    const int colB = (lane & 8) ? 4 : 0;

    const int z  = blockIdx.y;
    const int b  = z >> 4;
    const int h  = z & 15;
    const int q0 = blockIdx.x * FQ;

    const float* __restrict__ Qg = g_qkv + (size_t)(b * S + q0) * H3 + h * D;

    // ---- prologue: async Q + K0, mask, rowsums ----
#pragma unroll
    for (int j = 0; j < 8; j++) {
        int idx = tid + j * 256;
        int r = idx >> 5, c = (idx & 31) * 4;
        cp_async16(&sQ[r * QP + c], Qg + (size_t)r * H3 + c);
    }
    {
        const float* Kg0 = g_qkv + (size_t)(b * S) * H3 + H + h * D;
#pragma unroll
        for (int j = 0; j < 16; j++) {
            int idx = tid + j * 256;
            int r = idx >> 5, c = (idx & 31) * 4;
            cp_async16(&sK[r * KP + c], Kg0 + (size_t)r * H3 + c);
        }
    }
    cp_commit();
#pragma unroll
    for (int i = tid; i < S; i += 256) sMask[i] = mask[(size_t)b * S + i];
    if (tid < FQ) sRow[tid] = 0.0f;

    uint32_t aQAdr[2], aPAdr[2], bKAdr[2];
#pragma unroll
    for (int mi = 0; mi < 2; mi++) {
        aQAdr[mi] = smem_u32(sQ + (wm + mi * 16 + rowA) * QP + colA);
        aPAdr[mi] = smem_u32(sP + (wm + mi * 16 + rowA) * PP + colA);
    }
#pragma unroll
    for (int njp = 0; njp < 2; njp++)
        bKAdr[njp] = smem_u32(sK + (wn + njp * 16 + rowB) * KP + colB);

    const uint32_t* sVu = reinterpret_cast<const uint32_t*>(sV);

    float oacc[2][4][4];
#pragma unroll
    for (int mi = 0; mi < 2; mi++)
#pragma unroll
        for (int nj = 0; nj < 4; nj++)
#pragma unroll
            for (int r = 0; r < 4; r++) oacc[mi][nj][r] = 0.0f;

    for (int jt = 0; jt < S / 128; jt++) {
        const int n0 = jt * 128;

        cp_wait<0>();
        __syncthreads();

        // ---- prefetch V[jt] (overlaps QK) ----
        {
            const float* Vg = g_qkv + (size_t)(b * S + n0) * H3 + 2 * H + h * D;
#pragma unroll
            for (int j = 0; j < 16; j++) {
                int idx = tid + j * 256;
                int r = idx >> 5, c = (idx & 31) * 4;
                cp_async16(&sV[r * VP + c], Vg + (size_t)r * H3 + c);
            }
            cp_commit();
        }

        // ---- S = Q @ K^T ----
        float sacc[2][4][4];
#pragma unroll
        for (int mi = 0; mi < 2; mi++)
#pragma unroll
            for (int nj = 0; nj < 4; nj++)
#pragma unroll
                for (int r = 0; r < 4; r++) sacc[mi][nj][r] = 0.0f;

#pragma unroll
        for (int kk = 0; kk < D; kk += 8) {
            uint32_t a[2][4], bfr[2][4];
#pragma unroll
            for (int mi = 0; mi < 2; mi++)   ldm_x4(a[mi],   aQAdr[mi] + kk * 4);
#pragma unroll
            for (int njp = 0; njp < 2; njp++) ldm_x4(bfr[njp], bKAdr[njp] + kk * 4);
#pragma unroll
            for (int mi = 0; mi < 2; mi++)
#pragma unroll
                for (int nj = 0; nj < 4; nj++)
                    mma8u(sacc[mi][nj], a[mi], &bfr[nj >> 1][(nj & 1) * 2]);
        }

        // ---- P = exp(S*scale + mask) -> sP; rowsums ----
#pragma unroll
        for (int mi = 0; mi < 2; mi++) {
            const int r0 = wm + mi * 16 + g;
            float rp0 = 0.0f, rp1 = 0.0f;
#pragma unroll
            for (int nj = 0; nj < 4; nj++) {
                const int col = wn + nj * 8 + 2 * t;
                const float m0v = sMask[n0 + col];
                const float m1v = sMask[n0 + col + 1];
                float p00 = __expf(fmaf(sacc[mi][nj][0], SM_SCALE, m0v));
                float p01 = __expf(fmaf(sacc[mi][nj][1], SM_SCALE, m1v));
                float p10 = __expf(fmaf(sacc[mi][nj][2], SM_SCALE, m0v));
                float p11 = __expf(fmaf(sacc[mi][nj][3], SM_SCALE, m1v));
                rp0 += p00 + p01;
                rp1 += p10 + p11;
                *reinterpret_cast<float2*>(&sP[r0 * PP + col]) =
                    make_float2(f2tf(p00), f2tf(p01));
                *reinterpret_cast<float2*>(&sP[(r0 + 8) * PP + col]) =
                    make_float2(f2tf(p10), f2tf(p11));
            }
            rp0 += __shfl_xor_sync(0xffffffffu, rp0, 1);
            rp0 += __shfl_xor_sync(0xffffffffu, rp0, 2);
            rp1 += __shfl_xor_sync(0xffffffffu, rp1, 1);
            rp1 += __shfl_xor_sync(0xffffffffu, rp1, 2);
            if (t == 0) {
                atomicAdd(&sRow[r0], rp0);
                atomicAdd(&sRow[r0 + 8], rp1);
            }
        }

        cp_wait<0>();
        __syncthreads();

        // ---- prefetch K[jt+1] (overlaps PV) ----
        if (jt + 1 < S / 128) {
            const float* Kg = g_qkv + (size_t)(b * S + n0 + 128) * H3 + H + h * D;
#pragma unroll
            for (int j = 0; j < 16; j++) {
                int idx = tid + j * 256;
                int r = idx >> 5, c = (idx & 31) * 4;
                cp_async16(&sK[r * KP + c], Kg + (size_t)r * H3 + c);
            }
            cp_commit();
        }

        // ---- O += P @ V ----
#pragma unroll
        for (int kk = 0; kk < 128; kk += 8) {
            uint32_t a[2][4], bf[4][2];
#pragma unroll
            for (int mi = 0; mi < 2; mi++) ldm_x4(a[mi], aPAdr[mi] + kk * 4);
#pragma unroll
            for (int nj = 0; nj < 4; nj++) {
                const int col = wn + nj * 8 + g;
                bf[nj][0] = sVu[(kk + t) * VP + col];
                bf[nj][1] = sVu[(kk + t + 4) * VP + col];
            }
#pragma unroll
            for (int mi = 0; mi < 2; mi++)
#pragma unroll
                for (int nj = 0; nj < 4; nj++)
                    mma8u(oacc[mi][nj], a[mi], bf[nj]);
        }
    }

    // ---- epilogue ----
#pragma unroll
    for (int mi = 0; mi < 2; mi++) {
        const int r0 = wm + mi * 16 + g;
        const float inv0 = 1.0f / sRow[r0];
        const float inv1 = 1.0f / sRow[r0 + 8];
#pragma unroll
        for (int nj = 0; nj < 4; nj++) {
            const int col = wn + nj * 8 + 2 * t;
            float* dst = g_ctx + (size_t)(b * S + q0 + r0) * H + h * D + col;
            *reinterpret_cast<float2*>(dst) =
                make_float2(f2tf(oacc[mi][nj][0] * inv0), f2tf(oacc[mi][nj][1] * inv0));
            *reinterpret_cast<float2*>(dst + (size_t)8 * H) =
                make_float2(f2tf(oacc[mi][nj][2] * inv1), f2tf(oacc[mi][nj][3] * inv1));
        }
    }
}

// ---------------------------------------------------------------------------
// Launch
// ---------------------------------------------------------------------------
extern "C" void kernel_launch(void* const* d_in, const int* in_sizes, int n_in,
                              void* d_out, int out_size)
{
    const float* hidden = nullptr;
    const float* mask   = nullptr;
    const float* W_qkv  = nullptr;
    const float* b_qkv  = nullptr;
    const float* W_out  = nullptr;
    const float* b_out  = nullptr;

    for (int i = 0; i < n_in; i++) {
        switch (in_sizes[i]) {
            case 8388608:  hidden = (const float*)d_in[i]; break;
            case 4096:     mask   = (const float*)d_in[i]; break;
            case 12582912: W_qkv  = (const float*)d_in[i]; break;
            case 6144:     b_qkv  = (const float*)d_in[i]; break;
            case 4194304:  W_out  = (const float*)d_in[i]; break;
            case 2048:     b_out  = (const float*)d_in[i]; break;
            default: break;
        }
    }
    float* out = (float*)d_out;

    cudaFuncSetAttribute(flash_mma_kernel,
                         cudaFuncAttributeMaxDynamicSharedMemorySize,
                         FLASH_SMEM_BYTES);
    cudaFuncSetAttribute(gemm_ldm_kernel,
                         cudaFuncAttributeMaxDynamicSharedMemorySize,
                         GSMEM_BYTES);

    float* qkv_ptr;   cudaGetSymbolAddress((void**)&qkv_ptr,  g_qkv);
    float* ctx_ptr;   cudaGetSymbolAddress((void**)&ctx_ptr,  g_ctx);
    float* atf_ptr;   cudaGetSymbolAddress((void**)&atf_ptr,  g_atf);
    float* wqkvt_ptr; cudaGetSymbolAddress((void**)&wqkvt_ptr, g_wqkvt);
    float* woutt_ptr; cudaGetSymbolAddress((void**)&woutt_ptr, g_woutt);

    round_tf32_kernel<<<(M * H / 4 + 255) / 256, 256>>>(hidden, atf_ptr, M * H / 4);
    transpose_round_kernel<<<dim3(H3 / 32, H / 32), dim3(32, 8)>>>(W_qkv, wqkvt_ptr, H, H3);
    transpose_round_kernel<<<dim3(H / 32, H / 32), dim3(32, 8)>>>(W_out, woutt_ptr, H, H);

    // QKV projection (tf32-rounded output feeds flash's raw cp.async staging)
    gemm_ldm_kernel<<<dim3(H3 / 64, M / 128), 128, GSMEM_BYTES>>>(
        atf_ptr, H, wqkvt_ptr, H, qkv_ptr, H3, H, b_qkv, 1);

    flash_mma_kernel<<<dim3(S / FQ, B * NH), 256, FLASH_SMEM_BYTES>>>(mask);

    // output projection (full fp32 output)
    gemm_ldm_kernel<<<dim3(H / 64, M / 128), 128, GSMEM_BYTES>>>(
        ctx_ptr, H, woutt_ptr, H, out, H, H, b_out, 0);
}

// round 14
// speedup vs baseline: 1.9613x; 1.7294x over previous
#include <cuda_runtime.h>
#include <cuda_fp16.h>
#include <cstdint>

// ---------------------------------------------------------------------------
// Problem constants
// ---------------------------------------------------------------------------
constexpr int B   = 2;
constexpr int S   = 2048;
constexpr int H   = 2048;
constexpr int NH  = 16;
constexpr int D   = 128;
constexpr int M   = B * S;     // 4096
constexpr int H3  = 3 * H;     // 6144
constexpr float SM_SCALE = 0.08838834764831845f;  // 1/sqrt(128)

// ---------------------------------------------------------------------------
// Scratch (fp16 operands; fp32 only at the final output)
// ---------------------------------------------------------------------------
__device__ __half g_qkv[(size_t)M * H3];     // [4096, 6144]
__device__ __half g_ctx[(size_t)M * H];      // [4096, 2048]
__device__ __half g_ah [(size_t)M * H];      // hidden -> fp16
__device__ __half g_wqkvt[(size_t)H3 * H];   // W_qkv^T [6144][2048]
__device__ __half g_woutt[(size_t)H * H];    // W_out^T [2048][2048]

// ---------------------------------------------------------------------------
// Helpers (baseline PTX only — compiles at compute_100)
// ---------------------------------------------------------------------------
__device__ __forceinline__ uint32_t smem_u32(const void* p) {
    uint32_t a;
    asm("{ .reg .u64 t; cvta.to.shared.u64 t, %1; cvt.u32.u64 %0, t; }"
        : "=r"(a) : "l"(p));
    return a;
}
// fp16 mma: D(16x8,f32) = A(16x16,f16) * B(16x8,f16) + C
// A regs: a0=(g,2t:2t+1) a1=(g+8,2t:2t+1) a2=(g,8+2t:+1) a3=(g+8,8+2t:+1)
// B regs: b0=(k 2t:2t+1, n g)  b1=(k 8+2t:+1, n g)
// C regs: c0=(g,2t) c1=(g,2t+1) c2=(g+8,2t) c3=(g+8,2t+1)
__device__ __forceinline__ void mma16(float* d, const uint32_t* a, const uint32_t* b) {
    asm volatile(
        "mma.sync.aligned.m16n8k16.row.col.f32.f16.f16.f32 "
        "{%0,%1,%2,%3}, {%4,%5,%6,%7}, {%8,%9}, {%0,%1,%2,%3};\n"
        : "+f"(d[0]), "+f"(d[1]), "+f"(d[2]), "+f"(d[3])
        : "r"(a[0]), "r"(a[1]), "r"(a[2]), "r"(a[3]), "r"(b[0]), "r"(b[1]));
}
// x4 ldmatrix, b16. Shared address formula for ALL uses:
//   lane addr = base + ((lane&7)+(lane&8)) * stride + ((lane&16)?8:0) halfs
// plain:  on [row][k]  -> r0..r3 = A-frag  (row=m)  or B-frag pairs (row=n)
// trans:  on [k][col]  -> r0..r3 = B-frag with k in the pair position
__device__ __forceinline__ void ldm_x4(uint32_t* r, uint32_t addr) {
    asm volatile("ldmatrix.sync.aligned.m8n8.x4.shared.b16 {%0,%1,%2,%3}, [%4];"
                 : "=r"(r[0]), "=r"(r[1]), "=r"(r[2]), "=r"(r[3]) : "r"(addr));
}
__device__ __forceinline__ void ldm_x4_t(uint32_t* r, uint32_t addr) {
    asm volatile("ldmatrix.sync.aligned.m8n8.x4.trans.shared.b16 {%0,%1,%2,%3}, [%4];"
                 : "=r"(r[0]), "=r"(r[1]), "=r"(r[2]), "=r"(r[3]) : "r"(addr));
}
__device__ __forceinline__ void cp_async16(void* smem, const void* gmem) {
    uint32_t s = (uint32_t)__cvta_generic_to_shared(smem);
    asm volatile("cp.async.cg.shared.global [%0], [%1], 16;\n" :: "r"(s), "l"(gmem));
}
__device__ __forceinline__ void cp_commit() { asm volatile("cp.async.commit_group;\n"); }
template <int N>
__device__ __forceinline__ void cp_wait() {
    asm volatile("cp.async.wait_group %0;\n" :: "n"(N));
}

// ---------------------------------------------------------------------------
// Prologue 1: fp32 -> fp16 (hidden -> g_ah).  8 floats / thread.
// ---------------------------------------------------------------------------
__global__ void conv_half_kernel(const float* __restrict__ in,
                                 __half* __restrict__ out, int n8)
{
    int i = blockIdx.x * 256 + threadIdx.x;
    if (i < n8) {
        float4 v0 = reinterpret_cast<const float4*>(in)[2 * i];
        float4 v1 = reinterpret_cast<const float4*>(in)[2 * i + 1];
        __half2 h[4];
        h[0] = __floats2half2_rn(v0.x, v0.y);
        h[1] = __floats2half2_rn(v0.z, v0.w);
        h[2] = __floats2half2_rn(v1.x, v1.y);
        h[3] = __floats2half2_rn(v1.z, v1.w);
        reinterpret_cast<uint2*>(out)[2 * i]     = *reinterpret_cast<uint2*>(&h[0]);
        reinterpret_cast<uint2*>(out)[2 * i + 1] = *reinterpret_cast<uint2*>(&h[2]);
    }
}

// ---------------------------------------------------------------------------
// Prologue 2: W [K][N] fp32 -> Wt [N][K] fp16.  block (32,8)
// ---------------------------------------------------------------------------
__global__ void transpose_half_kernel(const float* __restrict__ W,
                                      __half* __restrict__ Wt, int K, int N)
{
    __shared__ float t[32][33];
    const int n0 = blockIdx.x * 32, k0 = blockIdx.y * 32;
    const int tx = threadIdx.x, ty = threadIdx.y;
#pragma unroll
    for (int j = 0; j < 4; j++)
        t[ty + 8 * j][tx] = W[(size_t)(k0 + ty + 8 * j) * N + n0 + tx];
    __syncthreads();
#pragma unroll
    for (int j = 0; j < 4; j++)
        Wt[(size_t)(n0 + ty + 8 * j) * K + k0 + tx] = __float2half_rn(t[tx][ty + 8 * j]);
}

// ---------------------------------------------------------------------------
// fp16 GEMM: C[128m x 64n per CTA] = A[M,K] @ Bt[N,K]^T + bias.
// 4 warps (64x32 each), k-chunk 64, 2-stage cp.async, ldmatrix x4.
// smem stride 72 halfs (144 B): 16B-units 9 mod 8 -> row permutation,
// conflict-free ldmatrix phases + aligned cp.async.
// out_half -> write fp16 (QKV); else fp32 (final output).
// ---------------------------------------------------------------------------
constexpr int SAH = 72;                       // halfs per row
constexpr int GA  = 128 * SAH;                // A tile halfs
constexpr int GB  = 64 * SAH;                 // B tile halfs
constexpr int GSTG = GA + GB;                 // per stage halfs
constexpr int GSMEM_BYTES = 2 * GSTG * 2;     // 55296 B

__global__ __launch_bounds__(128, 4)
void gemm_h_kernel(const __half* __restrict__ A,  int lda,
                   const __half* __restrict__ Bt, int ldbt,
                   void* __restrict__ Cv,         int ldc,
                   int K, const float* __restrict__ bias, int out_half)
{
    extern __shared__ __align__(16) __half sg[];

    const int tid  = threadIdx.x;
    const int warp = tid >> 5, lane = tid & 31;
    const int g = lane >> 2, t = lane & 3;
    const int wm = (warp >> 1) * 64, wn = (warp & 1) * 32;
    const int m0 = blockIdx.y * 128, n0 = blockIdx.x * 64;

    A  += (size_t)m0 * lda;
    Bt += (size_t)n0 * ldbt;

    const int rowL = (lane & 7) + (lane & 8);      // shared ldmatrix row map
    const int colL = (lane & 16) ? 8 : 0;          // halfs

    float acc[4][4][4];
#pragma unroll
    for (int mi = 0; mi < 4; mi++)
#pragma unroll
        for (int nj = 0; nj < 4; nj++)
#pragma unroll
            for (int r = 0; r < 4; r++) acc[mi][nj][r] = 0.0f;

    auto stage = [&](int kt, int buf) {
        __half* dA = sg + buf * GSTG;
        __half* dB = dA + GA;
        const int k0 = kt * 64;
#pragma unroll
        for (int j = 0; j < 8; j++) {              // A: 1024 chunks
            int idx = tid + j * 128;
            int r = idx >> 3, c = (idx & 7) * 8;
            cp_async16(&dA[r * SAH + c], A + (size_t)r * lda + k0 + c);
        }
#pragma unroll
        for (int j = 0; j < 4; j++) {              // B: 512 chunks
            int idx = tid + j * 128;
            int r = idx >> 3, c = (idx & 7) * 8;
            cp_async16(&dB[r * SAH + c], Bt + (size_t)r * ldbt + k0 + c);
        }
        cp_commit();
    };

    stage(0, 0);
    const int KT = K / 64;

    for (int kt = 0; kt < KT; kt++) {
        const int buf = kt & 1;
        if (kt + 1 < KT) { stage(kt + 1, buf ^ 1); cp_wait<1>(); }
        else             { cp_wait<0>(); }
        __syncthreads();

        const __half* cA = sg + buf * GSTG;
        const __half* cB = cA + GA;
        uint32_t aAdr[4], bAdr[2];
#pragma unroll
        for (int mi = 0; mi < 4; mi++)
            aAdr[mi] = smem_u32(cA + (wm + mi * 16 + rowL) * SAH + colL);
#pragma unroll
        for (int njp = 0; njp < 2; njp++)
            bAdr[njp] = smem_u32(cB + (wn + njp * 16 + rowL) * SAH + colL);

#pragma unroll
        for (int kk = 0; kk < 64; kk += 16) {
            uint32_t a[4][4], bfr[2][4];
#pragma unroll
            for (int mi = 0; mi < 4; mi++)   ldm_x4(a[mi],   aAdr[mi]  + kk * 2);
#pragma unroll
            for (int njp = 0; njp < 2; njp++) ldm_x4(bfr[njp], bAdr[njp] + kk * 2);
            // plain-B frag order: n-oct even -> {r0,r2}, odd -> {r1,r3}
#pragma unroll
            for (int mi = 0; mi < 4; mi++)
#pragma unroll
                for (int nj = 0; nj < 4; nj++) {
                    uint32_t bb[2] = { bfr[nj >> 1][nj & 1], bfr[nj >> 1][(nj & 1) + 2] };
                    mma16(acc[mi][nj], a[mi], bb);
                }
        }
        __syncthreads();
    }

    // epilogue
#pragma unroll
    for (int mi = 0; mi < 4; mi++) {
#pragma unroll
        for (int nj = 0; nj < 4; nj++) {
            const int row = wm + mi * 16 + g;
            const int col = wn + nj * 8 + 2 * t;
            const float b0 = bias ? bias[n0 + col]     : 0.0f;
            const float b1 = bias ? bias[n0 + col + 1] : 0.0f;
            float v0 = acc[mi][nj][0] + b0, v1 = acc[mi][nj][1] + b1;
            float v2 = acc[mi][nj][2] + b0, v3 = acc[mi][nj][3] + b1;
            if (out_half) {
                __half* C16 = (__half*)Cv + (size_t)m0 * ldc + n0;
                *reinterpret_cast<__half2*>(C16 + (size_t)row * ldc + col) =
                    __floats2half2_rn(v0, v1);
                *reinterpret_cast<__half2*>(C16 + (size_t)(row + 8) * ldc + col) =
                    __floats2half2_rn(v2, v3);
            } else {
                float* C32 = (float*)Cv + (size_t)m0 * ldc + n0;
                *reinterpret_cast<float2*>(C32 + (size_t)row * ldc + col) =
                    make_float2(v0, v1);
                *reinterpret_cast<float2*>(C32 + (size_t)(row + 8) * ldc + col) =
                    make_float2(v2, v3);
            }
        }
    }
}

// ---------------------------------------------------------------------------
// Fused flash attention, fp16 mma, cp.async pipelined (round-12 structure).
// Tiles (fp16, stride 136 halfs = 272 B; 16B-units 17 mod 8 -> permutation):
//   sQ[64][136], sK[128][136], sV[128][136], sP[64][136]  (~110 KB)
// QK: A=Q plain-x4, B=K plain-x4 ([key][d]).  PV: A=P plain-x4, B=V trans-x4
// ([k][d]; trans-B frag order: d-oct even -> {r0,r1}, odd -> {r2,r3}).
// 2 CTAs/SM via launch_bounds(256,2).
// ---------------------------------------------------------------------------
constexpr int FQ = 64;
constexpr int FP = 136;                       // halfs per row, all tiles
constexpr int FLASH_SMEM_BYTES =
    (FQ * FP + 128 * FP + 128 * FP + FQ * FP) * 2 + (FQ + S) * 4;  // ~113 KB

__global__ __launch_bounds__(256, 2)
void flash_h_kernel(const float* __restrict__ mask)
{
    extern __shared__ __align__(16) __half smh[];
    __half* sQ = smh;                         // [64][136]
    __half* sK = sQ + FQ * FP;                // [128][136]
    __half* sV = sK + 128 * FP;               // [128][136]
    __half* sP = sV + 128 * FP;               // [64][136]
    float* sRow  = reinterpret_cast<float*>(sP + FQ * FP);   // [64]
    float* sMask = sRow + FQ;                                // [2048]

    const int tid  = threadIdx.x;
    const int warp = tid >> 5, lane = tid & 31;
    const int g = lane >> 2, t = lane & 3;
    const int wm = (warp >> 2) * 32;
    const int wn = (warp & 3) * 32;

    const int rowL = (lane & 7) + (lane & 8);
    const int colL = (lane & 16) ? 8 : 0;

    const int z  = blockIdx.y;
    const int b  = z >> 4;
    const int h  = z & 15;
    const int q0 = blockIdx.x * FQ;

    const __half* __restrict__ Qg = g_qkv + (size_t)(b * S + q0) * H3 + h * D;

    // ---- prologue: async Q + K0, mask, rowsums ----
#pragma unroll
    for (int j = 0; j < 4; j++) {             // Q: 1024 chunks
        int idx = tid + j * 256;
        int r = idx >> 4, c = (idx & 15) * 8;
        cp_async16(&sQ[r * FP + c], Qg + (size_t)r * H3 + c);
    }
    {
        const __half* Kg0 = g_qkv + (size_t)(b * S) * H3 + H + h * D;
#pragma unroll
        for (int j = 0; j < 8; j++) {         // K: 2048 chunks
            int idx = tid + j * 256;
            int r = idx >> 4, c = (idx & 15) * 8;
            cp_async16(&sK[r * FP + c], Kg0 + (size_t)r * H3 + c);
        }
    }
    cp_commit();
#pragma unroll
    for (int i = tid; i < S; i += 256) sMask[i] = mask[(size_t)b * S + i];
    if (tid < FQ) sRow[tid] = 0.0f;

    uint32_t aQAdr[2], aPAdr[2], bKAdr[2], bVAdr[2];
#pragma unroll
    for (int mi = 0; mi < 2; mi++) {
        aQAdr[mi] = smem_u32(sQ + (wm + mi * 16 + rowL) * FP + colL);
        aPAdr[mi] = smem_u32(sP + (wm + mi * 16 + rowL) * FP + colL);
    }
#pragma unroll
    for (int njp = 0; njp < 2; njp++) {
        bKAdr[njp] = smem_u32(sK + (wn + njp * 16 + rowL) * FP + colL);
        bVAdr[njp] = smem_u32(sV + rowL * FP + wn + njp * 16 + colL);  // trans
    }

    float oacc[2][4][4];
#pragma unroll
    for (int mi = 0; mi < 2; mi++)
#pragma unroll
        for (int nj = 0; nj < 4; nj++)
#pragma unroll
            for (int r = 0; r < 4; r++) oacc[mi][nj][r] = 0.0f;

    for (int jt = 0; jt < S / 128; jt++) {
        const int n0 = jt * 128;

        cp_wait<0>();
        __syncthreads();

        // ---- prefetch V[jt] (overlaps QK) ----
        {
            const __half* Vg = g_qkv + (size_t)(b * S + n0) * H3 + 2 * H + h * D;
#pragma unroll
            for (int j = 0; j < 8; j++) {
                int idx = tid + j * 256;
                int r = idx >> 4, c = (idx & 15) * 8;
                cp_async16(&sV[r * FP + c], Vg + (size_t)r * H3 + c);
            }
            cp_commit();
        }

        // ---- S = Q @ K^T ----
        float sacc[2][4][4];
#pragma unroll
        for (int mi = 0; mi < 2; mi++)
#pragma unroll
            for (int nj = 0; nj < 4; nj++)
#pragma unroll
                for (int r = 0; r < 4; r++) sacc[mi][nj][r] = 0.0f;

#pragma unroll
        for (int kk = 0; kk < D; kk += 16) {
            uint32_t a[2][4], bfr[2][4];
#pragma unroll
            for (int mi = 0; mi < 2; mi++)   ldm_x4(a[mi],   aQAdr[mi] + kk * 2);
#pragma unroll
            for (int njp = 0; njp < 2; njp++) ldm_x4(bfr[njp], bKAdr[njp] + kk * 2);
#pragma unroll
            for (int mi = 0; mi < 2; mi++)
#pragma unroll
                for (int nj = 0; nj < 4; nj++) {
                    uint32_t bb[2] = { bfr[nj >> 1][nj & 1], bfr[nj >> 1][(nj & 1) + 2] };
                    mma16(sacc[mi][nj], a[mi], bb);
                }
        }

        // ---- P = exp(S*scale + mask) -> sP (fp16); rowsums ----
#pragma unroll
        for (int mi = 0; mi < 2; mi++) {
            const int r0 = wm + mi * 16 + g;
            float rp0 = 0.0f, rp1 = 0.0f;
#pragma unroll
            for (int nj = 0; nj < 4; nj++) {
                const int col = wn + nj * 8 + 2 * t;
                const float m0v = sMask[n0 + col];
                const float m1v = sMask[n0 + col + 1];
                float p00 = __expf(fmaf(sacc[mi][nj][0], SM_SCALE, m0v));
                float p01 = __expf(fmaf(sacc[mi][nj][1], SM_SCALE, m1v));
                float p10 = __expf(fmaf(sacc[mi][nj][2], SM_SCALE, m0v));
                float p11 = __expf(fmaf(sacc[mi][nj][3], SM_SCALE, m1v));
                rp0 += p00 + p01;
                rp1 += p10 + p11;
                *reinterpret_cast<__half2*>(&sP[r0 * FP + col]) =
                    __floats2half2_rn(p00, p01);
                *reinterpret_cast<__half2*>(&sP[(r0 + 8) * FP + col]) =
                    __floats2half2_rn(p10, p11);
            }
            rp0 += __shfl_xor_sync(0xffffffffu, rp0, 1);
            rp0 += __shfl_xor_sync(0xffffffffu, rp0, 2);
            rp1 += __shfl_xor_sync(0xffffffffu, rp1, 1);
            rp1 += __shfl_xor_sync(0xffffffffu, rp1, 2);
            if (t == 0) {
                atomicAdd(&sRow[r0], rp0);
                atomicAdd(&sRow[r0 + 8], rp1);
            }
        }

        cp_wait<0>();
        __syncthreads();

        // ---- prefetch K[jt+1] (overlaps PV) ----
        if (jt + 1 < S / 128) {
            const __half* Kg = g_qkv + (size_t)(b * S + n0 + 128) * H3 + H + h * D;
#pragma unroll
            for (int j = 0; j < 8; j++) {
                int idx = tid + j * 256;
                int r = idx >> 4, c = (idx & 15) * 8;
                cp_async16(&sK[r * FP + c], Kg + (size_t)r * H3 + c);
            }
            cp_commit();
        }

        // ---- O += P @ V : A=P plain-x4, B=V trans-x4 ----
#pragma unroll
        for (int kk = 0; kk < 128; kk += 16) {
            uint32_t a[2][4], bfr[2][4];
#pragma unroll
            for (int mi = 0; mi < 2; mi++) ldm_x4(a[mi], aPAdr[mi] + kk * 2);
#pragma unroll
            for (int njp = 0; njp < 2; njp++)
                ldm_x4_t(bfr[njp], bVAdr[njp] + kk * (FP * 2));
#pragma unroll
            for (int mi = 0; mi < 2; mi++)
#pragma unroll
                for (int nj = 0; nj < 4; nj++)
                    mma16(oacc[mi][nj], a[mi], &bfr[nj >> 1][(nj & 1) * 2]);
        }
    }

    // ---- epilogue: normalize, store ctx fp16 ----
#pragma unroll
    for (int mi = 0; mi < 2; mi++) {
        const int r0 = wm + mi * 16 + g;
        const float inv0 = 1.0f / sRow[r0];
        const float inv1 = 1.0f / sRow[r0 + 8];
#pragma unroll
        for (int nj = 0; nj < 4; nj++) {
            const int col = wn + nj * 8 + 2 * t;
            __half* dst = g_ctx + (size_t)(b * S + q0 + r0) * H + h * D + col;
            *reinterpret_cast<__half2*>(dst) =
                __floats2half2_rn(oacc[mi][nj][0] * inv0, oacc[mi][nj][1] * inv0);
            *reinterpret_cast<__half2*>(dst + (size_t)8 * H) =
                __floats2half2_rn(oacc[mi][nj][2] * inv1, oacc[mi][nj][3] * inv1);
        }
    }
}

// ---------------------------------------------------------------------------
// Launch
// ---------------------------------------------------------------------------
extern "C" void kernel_launch(void* const* d_in, const int* in_sizes, int n_in,
                              void* d_out, int out_size)
{
    const float* hidden = nullptr;
    const float* mask   = nullptr;
    const float* W_qkv  = nullptr;
    const float* b_qkv  = nullptr;
    const float* W_out  = nullptr;
    const float* b_out  = nullptr;

    for (int i = 0; i < n_in; i++) {
        switch (in_sizes[i]) {
            case 8388608:  hidden = (const float*)d_in[i]; break;
            case 4096:     mask   = (const float*)d_in[i]; break;
            case 12582912: W_qkv  = (const float*)d_in[i]; break;
            case 6144:     b_qkv  = (const float*)d_in[i]; break;
            case 4194304:  W_out  = (const float*)d_in[i]; break;
            case 2048:     b_out  = (const float*)d_in[i]; break;
            default: break;
        }
    }
    float* out = (float*)d_out;

    cudaFuncSetAttribute(flash_h_kernel,
                         cudaFuncAttributeMaxDynamicSharedMemorySize,
                         FLASH_SMEM_BYTES);
    cudaFuncSetAttribute(gemm_h_kernel,
                         cudaFuncAttributeMaxDynamicSharedMemorySize,
                         GSMEM_BYTES);

    __half* qkv_ptr;   cudaGetSymbolAddress((void**)&qkv_ptr,  g_qkv);
    __half* ctx_ptr;   cudaGetSymbolAddress((void**)&ctx_ptr,  g_ctx);
    __half* ah_ptr;    cudaGetSymbolAddress((void**)&ah_ptr,   g_ah);
    __half* wqkvt_ptr; cudaGetSymbolAddress((void**)&wqkvt_ptr, g_wqkvt);
    __half* woutt_ptr; cudaGetSymbolAddress((void**)&woutt_ptr, g_woutt);

    conv_half_kernel<<<(M * H / 8 + 255) / 256, 256>>>(hidden, ah_ptr, M * H / 8);
    transpose_half_kernel<<<dim3(H3 / 32, H / 32), dim3(32, 8)>>>(W_qkv, wqkvt_ptr, H, H3);
    transpose_half_kernel<<<dim3(H / 32, H / 32), dim3(32, 8)>>>(W_out, woutt_ptr, H, H);

    // QKV projection (fp16 output)
    gemm_h_kernel<<<dim3(H3 / 64, M / 128), 128, GSMEM_BYTES>>>(
        ah_ptr, H, wqkvt_ptr, H, qkv_ptr, H3, H, b_qkv, 1);

    flash_h_kernel<<<dim3(S / FQ, B * NH), 256, FLASH_SMEM_BYTES>>>(mask);

    // output projection (fp32 output)
    gemm_h_kernel<<<dim3(H / 64, M / 128), 128, GSMEM_BYTES>>>(
        ctx_ptr, H, woutt_ptr, H, out, H, H, b_out, 0);
}